// round 12
// baseline (speedup 1.0000x reference)
#include <cuda_runtime.h>
#include <cuda_bf16.h>
#include <cstdint>
#include <math.h>

#define BB 2
#define HH 16
#define SQ 2048
#define DDIM 64
#define MQ 128
#define NTH 256
#define C_SCALE 0.18033688011110543f   // 0.125 * log2(e)

// smem layout (u32 units)
#define U_KH 0                 // pass2: [2][2048]; pass1: bufs [2][4096]
#define U_KL 4096
#define U_VH 8192
#define U_VL 12288
#define U_IDX 16384            // pass1: [2][128] int; pass2: [2][64] int
#define SMEM_BYTES (16640 * 4)

// global scratch: frag-native pre-split COMPACTED K/V (hi/lo bf16x2)
__device__ uint32_t g_KH[32 * 16 * 4096];
__device__ uint32_t g_KL[32 * 16 * 4096];
__device__ uint32_t g_VH[32 * 16 * 4096];
__device__ uint32_t g_VL[32 * 16 * 4096];
__device__ int g_idx[BB][SQ];
__device__ int g_N[BB];

static __device__ __forceinline__ uint32_t smem_u32(const void* p) {
    uint32_t a;
    asm("{ .reg .u64 t; cvta.to.shared.u64 t, %1; cvt.u32.u64 %0, t; }" : "=r"(a) : "l"(p));
    return a;
}
static __device__ __forceinline__ void cp16(uint32_t dst, const void* src) {
    asm volatile("cp.async.cg.shared.global [%0], [%1], 16;" :: "r"(dst), "l"(src));
}
#define CP_COMMIT() asm volatile("cp.async.commit_group;" ::: "memory")
#define CP_WAIT0()  asm volatile("cp.async.wait_group 0;" ::: "memory")

static __device__ __forceinline__ float ex2f(float x) {
    float y; asm("ex2.approx.f32 %0, %1;" : "=f"(y) : "f"(x)); return y;
}
static __device__ __forceinline__ float lg2f(float x) {
    float y; asm("lg2.approx.f32 %0, %1;" : "=f"(y) : "f"(x)); return y;
}

static __device__ __forceinline__ void mma_bf16(float* c, const uint32_t* a, const uint32_t* b) {
    asm volatile(
        "mma.sync.aligned.m16n8k16.row.col.f32.bf16.bf16.f32 "
        "{%0,%1,%2,%3}, {%4,%5,%6,%7}, {%8,%9}, {%0,%1,%2,%3};"
        : "+f"(c[0]), "+f"(c[1]), "+f"(c[2]), "+f"(c[3])
        : "r"(a[0]), "r"(a[1]), "r"(a[2]), "r"(a[3]), "r"(b[0]), "r"(b[1]));
}

static __device__ __forceinline__ void split2(float a, float b, uint32_t& hi, uint32_t& lo) {
    __nv_bfloat162 h = __floats2bfloat162_rn(a, b);
    float ra = a - __bfloat162float(__low2bfloat16(h));
    float rb = b - __bfloat162float(__high2bfloat16(h));
    __nv_bfloat162 l = __floats2bfloat162_rn(ra, rb);
    hi = *reinterpret_cast<uint32_t*>(&h);
    lo = *reinterpret_cast<uint32_t*>(&l);
}

// ---------- prep A: build compacted key index per batch ----------
__global__ __launch_bounds__(1024)
void prep_index(const int* __restrict__ M) {
    const int b = blockIdx.x;
    const int t = threadIdx.x;
    __shared__ int a[1024];
    int m0 = M[b * SQ + 2 * t];
    int m1 = M[b * SQ + 2 * t + 1];
    a[t] = m0 + m1;
    __syncthreads();
    for (int off = 1; off < 1024; off <<= 1) {
        int v = a[t];
        if (t >= off) v += a[t - off];
        __syncthreads();
        a[t] = v;
        __syncthreads();
    }
    int total = a[1023];
    int excl = a[t] - (m0 + m1);
    if (m0) g_idx[b][excl] = 2 * t;
    if (m1) g_idx[b][excl + m0] = 2 * t + 1;
    for (int i = t; i < SQ; i += 1024)
        if (i >= total) g_idx[b][i] = -1;
    if (t == 0) g_N[b] = total;
}

// ---------- prep B: gather+split compacted K/V into frag-native scratch ----------
__global__ __launch_bounds__(1024)
void prep_split(const float* __restrict__ K, const float* __restrict__ V) {
    const int tile = blockIdx.x;                // bh*16 + compact 128-key tile
    const int bh = tile >> 4;
    const int b  = bh / HH;
    const int tloc = tile & 15;
    const int t = threadIdx.x;
    if (blockIdx.y == 0) {
        uint32_t* dH = g_KH + (size_t)tile * 4096;
        uint32_t* dL = g_KL + (size_t)tile * 4096;
        #pragma unroll
        for (int i = 0; i < 4; i++) {
            int idx = i * 1024 + t;
            int key = idx >> 5, dp = idx & 31;
            int orig = g_idx[b][tloc * 128 + key];
            float2 x = make_float2(0.f, 0.f);
            if (orig >= 0)
                x = ((const float2*)(K + ((size_t)bh * SQ + orig) * DDIM))[dp];
            int slot = (key >> 3) * 256 + (dp >> 3) * 64
                     + ((key & 7) * 4 + (dp & 3)) * 2 + ((dp >> 2) & 1);
            uint32_t hi, lo; split2(x.x, x.y, hi, lo);
            dH[slot] = hi; dL[slot] = lo;
        }
    } else {
        uint32_t* dH = g_VH + (size_t)tile * 4096;
        uint32_t* dL = g_VL + (size_t)tile * 4096;
        #pragma unroll
        for (int i = 0; i < 4; i++) {
            int idx = i * 1024 + t;
            int d = idx & 63, kp = idx >> 6;
            int o0 = g_idx[b][tloc * 128 + 2 * kp];
            int o1 = g_idx[b][tloc * 128 + 2 * kp + 1];
            float va = (o0 >= 0) ? V[((size_t)bh * SQ + o0) * DDIM + d] : 0.f;
            float vb = (o1 >= 0) ? V[((size_t)bh * SQ + o1) * DDIM + d] : 0.f;
            int kc2 = kp >> 3, w8 = kp & 7;
            int slot = kc2 * 512 + (d >> 3) * 64
                     + ((d & 7) * 4 + (w8 & 3)) * 2 + (w8 >> 2);
            uint32_t hi, lo; split2(va, vb, hi, lo);
            dH[slot] = hi; dL[slot] = lo;
        }
    }
}

// ---------- main attention kernel: 8 warps, 2 CTAs/SM, compacted keys ----------
__global__ __launch_bounds__(NTH, 2)
void attn12(const float* __restrict__ Q,
            float* __restrict__ Out, float* __restrict__ W) {
    extern __shared__ __align__(16) uint32_t smu[];
    const uint32_t sb = smem_u32(smu);

    const int t    = threadIdx.x;
    const int lane = t & 31;
    const int wid  = t >> 5;
    const int g    = lane >> 2;
    const int t4   = lane & 3;
    const int dlo  = 2 * t4;
    const int qb   = wid * 16;

    const int qt = blockIdx.x;
    const int bh = blockIdx.y;
    const int b  = bh / HH;

    const float* qg = Q + ((size_t)bh * SQ + (size_t)qt * MQ) * DDIM;
    const int N = g_N[b];
    const int nt1 = (N + 127) >> 7;        // pass-1 128-key compact tiles
    const int nt2 = (N + 63) >> 6;         // pass-2 64-key compact tiles

    // ---- pass-1 prefetchers ----
    auto pfK1 = [&](int buf, int bt) {
        const uint32_t* sH = g_KH + ((size_t)bh * 16 + bt) * 4096;
        const uint32_t d = sb + (uint32_t)buf * 4096 * 4;
        #pragma unroll
        for (int c = 0; c < 4; c++) {
            int o = (c * NTH + t) * 4;
            cp16(d + o * 4, sH + o);
        }
    };
    auto pfI1 = [&](int buf, int bt) {
        if (t < 32) cp16(sb + (U_IDX + buf * 128 + t * 4) * 4, &g_idx[b][bt * 128 + t * 4]);
    };
    // ---- pass-2 prefetchers ----
    auto pfK = [&](int buf, int kt64) {
        const size_t off = ((size_t)bh * 16 + (kt64 >> 1)) * 4096 + (size_t)(kt64 & 1) * 2048;
        const uint32_t* sH = g_KH + off;
        const uint32_t* sL = g_KL + off;
        const uint32_t dH = sb + (U_KH + buf * 2048) * 4;
        const uint32_t dL = sb + (U_KL + buf * 2048) * 4;
        #pragma unroll
        for (int c = 0; c < 2; c++) {
            int o = (c * NTH + t) * 4;
            cp16(dH + o * 4, sH + o);
            cp16(dL + o * 4, sL + o);
        }
    };
    auto pfV = [&](int buf, int kt64) {
        const size_t off = ((size_t)bh * 16 + (kt64 >> 1)) * 4096 + (size_t)(kt64 & 1) * 2048;
        const uint32_t* sH = g_VH + off;
        const uint32_t* sL = g_VL + off;
        const uint32_t dH = sb + (U_VH + buf * 2048) * 4;
        const uint32_t dL = sb + (U_VL + buf * 2048) * 4;
        #pragma unroll
        for (int c = 0; c < 2; c++) {
            int o = (c * NTH + t) * 4;
            cp16(dH + o * 4, sH + o);
            cp16(dL + o * 4, sL + o);
        }
    };
    auto pfI2 = [&](int buf, int kt64) {
        if (t < 16) cp16(sb + (U_IDX + buf * 64 + t * 4) * 4, &g_idx[b][kt64 * 64 + t * 4]);
    };

    // kick off pass-1 tile 0
    pfK1(0, 0); pfI1(0, 0); CP_COMMIT();

    // ---- zero-fill this CTA's W strip (coalesced) ----
    {
        float4 z = make_float4(0.f, 0.f, 0.f, 0.f);
        float4* wz = (float4*)(W + ((size_t)bh * SQ + (size_t)qt * MQ) * SQ);
        #pragma unroll 8
        for (int i = 0; i < 256; i++) wz[i * NTH + t] = z;
    }

    // ---- persistent Q A-fragments (hi/lo) ----
    uint32_t AH[4][4], AL[4][4];
    #pragma unroll
    for (int kc = 0; kc < 4; kc++) {
        const float* r0 = qg + (size_t)(qb + g) * DDIM + kc * 16 + dlo;
        const float* r1 = r0 + 8 * DDIM;
        float2 p0 = *(const float2*)(r0);
        float2 p1 = *(const float2*)(r1);
        float2 p2 = *(const float2*)(r0 + 8);
        float2 p3 = *(const float2*)(r1 + 8);
        split2(p0.x, p0.y, AH[kc][0], AL[kc][0]);
        split2(p1.x, p1.y, AH[kc][1], AL[kc][1]);
        split2(p2.x, p2.y, AH[kc][2], AL[kc][2]);
        split2(p3.x, p3.y, AH[kc][3], AL[kc][3]);
    }

    auto qk1 = [&](const uint32_t* KHb, int kc2, float (&c)[2][4]) {
        #pragma unroll
        for (int nt = 0; nt < 2; nt++)
            c[nt][0] = c[nt][1] = c[nt][2] = c[nt][3] = 0.f;
        #pragma unroll
        for (int kcd = 0; kcd < 4; kcd++) {
            #pragma unroll
            for (int nt = 0; nt < 2; nt++) {
                int base = (kc2 * 2 + nt) * 256 + kcd * 64 + lane * 2;
                uint32_t bh2[2];
                *(uint2*)bh2 = *(const uint2*)&KHb[base];
                mma_bf16(c[nt], AH[kcd], bh2);
            }
        }
    };
    auto qk3 = [&](const uint32_t* KHb, const uint32_t* KLb, int kc2, float (&c)[2][2][4]) {
        #pragma unroll
        for (int nt = 0; nt < 2; nt++)
            #pragma unroll
            for (int s = 0; s < 2; s++)
                c[nt][s][0] = c[nt][s][1] = c[nt][s][2] = c[nt][s][3] = 0.f;
        #pragma unroll
        for (int kcd = 0; kcd < 4; kcd++) {
            #pragma unroll
            for (int nt = 0; nt < 2; nt++) {
                int base = (kc2 * 2 + nt) * 256 + kcd * 64 + lane * 2;
                uint32_t bh2[2], bl2[2];
                *(uint2*)bh2 = *(const uint2*)&KHb[base];
                *(uint2*)bl2 = *(const uint2*)&KLb[base];
                mma_bf16(c[nt][0], AH[kcd], bh2);
                mma_bf16(c[nt][1], AH[kcd], bl2);
                mma_bf16(c[nt][1], AL[kcd], bh2);
            }
        }
    };

    // ================= PASS 1: row sums (1-term QK, compacted 128-key tiles) =================
    float rs0 = 0.f, rs1 = 0.f;
    for (int bt = 0; bt < nt1; bt++) {
        const int cur = bt & 1;
        CP_WAIT0();
        __syncthreads();
        if (bt < nt1 - 1) {
            pfK1(cur ^ 1, bt + 1); pfI1(cur ^ 1, bt + 1);
            CP_COMMIT();
        }

        const uint32_t* KHb = smu + cur * 4096;
        const int* ix = (const int*)(smu + U_IDX + cur * 128);

        #pragma unroll
        for (int kc2 = 0; kc2 < 8; kc2++) {
            float c[2][4];
            qk1(KHb, kc2, c);
            int key0 = kc2 * 16 + dlo;
            int m0 = ix[key0], m1 = ix[key0 + 1], m2 = ix[key0 + 8], m3 = ix[key0 + 9];
            rs0 += (m0 >= 0 ? ex2f(c[0][0] * C_SCALE) : 0.f)
                 + (m1 >= 0 ? ex2f(c[0][1] * C_SCALE) : 0.f)
                 + (m2 >= 0 ? ex2f(c[1][0] * C_SCALE) : 0.f)
                 + (m3 >= 0 ? ex2f(c[1][1] * C_SCALE) : 0.f);
            rs1 += (m0 >= 0 ? ex2f(c[0][2] * C_SCALE) : 0.f)
                 + (m1 >= 0 ? ex2f(c[0][3] * C_SCALE) : 0.f)
                 + (m2 >= 0 ? ex2f(c[1][2] * C_SCALE) : 0.f)
                 + (m3 >= 0 ? ex2f(c[1][3] * C_SCALE) : 0.f);
        }
    }
    rs0 += __shfl_xor_sync(0xffffffffu, rs0, 1);
    rs0 += __shfl_xor_sync(0xffffffffu, rs0, 2);
    rs1 += __shfl_xor_sync(0xffffffffu, rs1, 1);
    rs1 += __shfl_xor_sync(0xffffffffu, rs1, 2);
    const float li0 = -lg2f(rs0);
    const float li1 = -lg2f(rs1);

    // pass-1 buffers overlap pass-2's KL region: retire pass-1 reads first
    __syncthreads();
    pfK(0, 0); pfV(0, 0); pfI2(0, 0); CP_COMMIT();

    float accO[8][4];
    #pragma unroll
    for (int j = 0; j < 8; j++)
        accO[j][0] = accO[j][1] = accO[j][2] = accO[j][3] = 0.f;

    float* wr0 = W + ((size_t)bh * SQ + qt * MQ + qb + g) * SQ;
    float* wr1 = wr0 + (size_t)8 * SQ;

    // ================= PASS 2: W scatter + PV (compacted 64-key tiles) =================
    for (int kt = 0; kt < nt2; kt++) {
        const int cur = kt & 1;
        CP_WAIT0();
        __syncthreads();
        if (kt < nt2 - 1) {
            pfK(cur ^ 1, kt + 1); pfV(cur ^ 1, kt + 1); pfI2(cur ^ 1, kt + 1);
            CP_COMMIT();
        }

        const uint32_t* KHb = smu + U_KH + cur * 2048;
        const uint32_t* KLb = smu + U_KL + cur * 2048;
        const uint32_t* VHb = smu + U_VH + cur * 2048;
        const uint32_t* VLb = smu + U_VL + cur * 2048;
        const int* ix = (const int*)(smu + U_IDX + cur * 64);

        #pragma unroll
        for (int kc2 = 0; kc2 < 4; kc2++) {
            float c[2][2][4];
            qk3(KHb, KLb, kc2, c);

            int key0 = kc2 * 16 + dlo;
            int2 ia = *(const int2*)&ix[key0];
            int2 ib = *(const int2*)&ix[key0 + 8];

            float e00 = ia.x >= 0 ? ex2f(fmaf(c[0][0][0] + c[0][1][0], C_SCALE, li0)) : 0.f;
            float e01 = ia.y >= 0 ? ex2f(fmaf(c[0][0][1] + c[0][1][1], C_SCALE, li0)) : 0.f;
            float e02 = ia.x >= 0 ? ex2f(fmaf(c[0][0][2] + c[0][1][2], C_SCALE, li1)) : 0.f;
            float e03 = ia.y >= 0 ? ex2f(fmaf(c[0][0][3] + c[0][1][3], C_SCALE, li1)) : 0.f;
            float e10 = ib.x >= 0 ? ex2f(fmaf(c[1][0][0] + c[1][1][0], C_SCALE, li0)) : 0.f;
            float e11 = ib.y >= 0 ? ex2f(fmaf(c[1][0][1] + c[1][1][1], C_SCALE, li0)) : 0.f;
            float e12 = ib.x >= 0 ? ex2f(fmaf(c[1][0][2] + c[1][1][2], C_SCALE, li1)) : 0.f;
            float e13 = ib.y >= 0 ? ex2f(fmaf(c[1][0][3] + c[1][1][3], C_SCALE, li1)) : 0.f;

            // scatter to original key positions (zeros pre-filled)
            if (ia.x >= 0) { wr0[ia.x] = e00; wr1[ia.x] = e02; }
            if (ia.y >= 0) { wr0[ia.y] = e01; wr1[ia.y] = e03; }
            if (ib.x >= 0) { wr0[ib.x] = e10; wr1[ib.x] = e12; }
            if (ib.y >= 0) { wr0[ib.y] = e11; wr1[ib.y] = e13; }

            uint32_t aWH[4], aWL[4];
            split2(e00, e01, aWH[0], aWL[0]);
            split2(e02, e03, aWH[1], aWL[1]);
            split2(e10, e11, aWH[2], aWL[2]);
            split2(e12, e13, aWH[3], aWL[3]);

            #pragma unroll
            for (int ntd = 0; ntd < 8; ntd++) {
                int base = kc2 * 512 + ntd * 64 + lane * 2;
                uint32_t bh2[2], bl2[2];
                *(uint2*)bh2 = *(const uint2*)&VHb[base];
                *(uint2*)bl2 = *(const uint2*)&VLb[base];
                mma_bf16(accO[ntd], aWH, bh2);
                mma_bf16(accO[ntd], aWL, bh2);
                mma_bf16(accO[ntd], aWH, bl2);
            }
        }
    }

    // ---- output (warp-owned, direct) ----
    float* or0 = Out + ((size_t)bh * SQ + qt * MQ + qb + g) * DDIM + dlo;
    float* or1 = or0 + (size_t)8 * DDIM;
    #pragma unroll
    for (int ntd = 0; ntd < 8; ntd++) {
        *(float2*)(or0 + ntd * 8) = make_float2(accO[ntd][0], accO[ntd][1]);
        *(float2*)(or1 + ntd * 8) = make_float2(accO[ntd][2], accO[ntd][3]);
    }
}

extern "C" void kernel_launch(void* const* d_in, const int* in_sizes, int n_in,
                              void* d_out, int out_size) {
    const float* q = (const float*)d_in[0];
    const float* k = (const float*)d_in[1];
    const float* v = (const float*)d_in[2];
    const int*   m = (const int*)d_in[3];

    float* out = (float*)d_out;
    float* wts = out + (size_t)BB * HH * SQ * DDIM;

    prep_index<<<BB, 1024>>>(m);
    dim3 pgrid(BB * HH * 16, 2);
    prep_split<<<pgrid, 1024>>>(k, v);

    cudaFuncSetAttribute(attn12, cudaFuncAttributeMaxDynamicSharedMemorySize, SMEM_BYTES);
    dim3 grid(SQ / MQ, BB * HH);
    attn12<<<grid, NTH, SMEM_BYTES>>>(q, out, wts);
}